// round 3
// baseline (speedup 1.0000x reference)
#include <cuda_runtime.h>
#include <math.h>
#include <float.h>

#define BB 16
#define SS 64
#define MM 2048
#define DD 256
#define TK 8
#define OV 512
#define NBLK 128
#define SCALE 0.0625f

// state (re-initialized every launch; no runtime allocs)
__device__ float g_ovl[BB*OV*DD];     // copy-on-write overlay rows (8MB)
__device__ int   g_slot[BB*MM];       // -1 or overlay slot
__device__ int   g_ovcnt[BB];
__device__ float g_qk[SS*BB*DD];      // scale*(Wk^T Wq xt + Wk^T bq), all steps
__device__ float g_gx[SS*BB*DD];      // Wu1 xt + bu, all steps
__device__ float g_AT[DD*DD];         // [j][d] = scale*(Wk^T Wq)[d][j]... stored j-major
__device__ float g_avec[DD];
__device__ float g_WuT1[DD*DD];
__device__ float g_WuT2[DD*DD];
__device__ float g_WvT[DD*DD];
__device__ float g_scores[BB*MM];
__device__ float g_pmax[NBLK*BB];
__device__ float g_psum[NBLK*BB];
__device__ float g_partial[NBLK*BB*DD];  // 2MB

// ---------------- init ----------------

__global__ void p_trans(const float* __restrict__ Wv, const float* __restrict__ Wu){
  __shared__ float tile[32][33];
  int which = blockIdx.z;
  const float* src; int stride; float* dst;
  if (which==0){ src=Wv; stride=DD;   dst=g_WvT;  }
  else if (which==1){ src=Wu; stride=2*DD; dst=g_WuT1; }
  else { src=Wu+DD; stride=2*DD; dst=g_WuT2; }
  int bi=blockIdx.x*32, bj=blockIdx.y*32;
  int tx=threadIdx.x, ty=threadIdx.y;
  #pragma unroll
  for (int k=0;k<32;k+=8) tile[ty+k][tx] = src[(size_t)(bi+ty+k)*stride + bj+tx];
  __syncthreads();
  #pragma unroll
  for (int k=0;k<32;k+=8) dst[(size_t)(bj+ty+k)*DD + bi+tx] = tile[tx][ty+k];
}

__global__ void p_A(const float* __restrict__ Wq, const float* __restrict__ Wk,
                    const float* __restrict__ bq){
  __shared__ float col[DD];
  int j = blockIdx.x, tid = threadIdx.x;
  col[tid] = (j < DD) ? Wq[(size_t)tid*DD + j] : bq[tid];
  __syncthreads();
  float acc = 0.f;
  #pragma unroll 4
  for (int i=0;i<DD;i++) acc = fmaf(Wk[(size_t)i*DD+tid], col[i], acc);
  if (j < DD) g_AT[j*DD+tid] = acc*SCALE;
  else        g_avec[tid]    = acc*SCALE;
}

__global__ void p_slot(){
  int i = blockIdx.x*256 + threadIdx.x;
  if (i < BB*MM) g_slot[i] = -1;
  if (i < BB)    g_ovcnt[i] = 0;
}

__global__ void p_qk(const float* __restrict__ x, const float* __restrict__ bu){
  __shared__ float xs[BB][DD];
  int t = blockIdx.x, which = blockIdx.y, tid = threadIdx.x;
  for (int i=tid;i<BB*DD;i+=256){ int b=i>>8, j=i&255; xs[b][j] = x[((size_t)b*SS+t)*DD + j]; }
  __syncthreads();
  const float* W = (which==0) ? g_AT : g_WuT1;
  float acc[BB];
  #pragma unroll
  for (int b=0;b<BB;b++) acc[b]=0.f;
  for (int j=0;j<DD;j++){
    float w = W[j*DD+tid];
    #pragma unroll
    for (int b=0;b<BB;b++) acc[b] = fmaf(w, xs[b][j], acc[b]);
  }
  if (which==0){
    float av = g_avec[tid];
    #pragma unroll
    for (int b=0;b<BB;b++) g_qk[((size_t)t*BB+b)*DD+tid] = acc[b]+av;
  } else {
    float bb = bu[tid];
    #pragma unroll
    for (int b=0;b<BB;b++) g_gx[((size_t)t*BB+b)*DD+tid] = acc[b]+bb;
  }
}

// ---------------- per-step ----------------

// scores + dirty fix + per-block softmax partials
__global__ void k1(const float* __restrict__ base, int t){
  __shared__ float rows[16][257];
  __shared__ float qks[16][257];
  __shared__ float sc[16][17];
  __shared__ int dlist[256];
  __shared__ int dcnt;
  int blk = blockIdx.x, m0 = blk*16, tid = threadIdx.x;
  for (int i=tid;i<16*DD;i+=256){ int r=i>>8, j=i&255; rows[r][j] = base[(size_t)(m0+r)*DD + j]; }
  const float* qkt = g_qk + (size_t)t*BB*DD;
  for (int i=tid;i<16*DD;i+=256){ int b=i>>8, j=i&255; qks[b][j] = qkt[i]; }
  if (tid==0) dcnt = 0;
  __syncthreads();
  int b = tid&15, r = tid>>4;
  float acc = 0.f;
  #pragma unroll 8
  for (int j=0;j<DD;j++) acc = fmaf(rows[r][j], qks[b][j], acc);
  sc[b][r] = acc;
  int s = g_slot[b*MM + m0 + r];
  if (s >= 0){ int p = atomicAdd(&dcnt,1); dlist[p] = (b<<16)|(r<<12)|s; }
  __syncthreads();
  int wid = tid>>5, lane = tid&31;
  int dn = dcnt;
  for (int e=wid; e<dn; e+=8){
    int pk = dlist[e]; int eb = pk>>16, er = (pk>>12)&15, es = pk&0xfff;
    const float* ov = g_ovl + ((size_t)eb*OV + es)*DD;
    float a2 = 0.f;
    #pragma unroll
    for (int k=0;k<8;k++) a2 = fmaf(ov[lane+32*k], qks[eb][lane+32*k], a2);
    #pragma unroll
    for (int off=16; off; off>>=1) a2 += __shfl_xor_sync(0xffffffffu, a2, off);
    if (lane==0) sc[eb][er] = a2;
  }
  __syncthreads();
  g_scores[b*MM + m0 + r] = sc[b][r];
  if (tid < 16){
    float mx = -FLT_MAX;
    #pragma unroll
    for (int rr=0;rr<16;rr++) mx = fmaxf(mx, sc[tid][rr]);
    float sm = 0.f;
    #pragma unroll
    for (int rr=0;rr<16;rr++) sm += expf(sc[tid][rr]-mx);
    g_pmax[blk*16+tid] = mx;
    g_psum[blk*16+tid] = sm;
  }
}

// combine softmax stats; attn for own rows; h partials (base + dirty corrections)
__global__ void k3(const float* __restrict__ base, int t){
  __shared__ float rows[16][257];
  __shared__ float attn_s[16][17];
  __shared__ float spart[16][DD];
  __shared__ float red2[16][17];
  __shared__ float sgm[16], sginv[16];
  __shared__ int dlist[256];
  __shared__ int dcnt;
  int blk = blockIdx.x, m0 = blk*16, tid = threadIdx.x;
  for (int i=tid;i<16*DD;i+=256){ int r=i>>8, j=i&255; rows[r][j] = base[(size_t)(m0+r)*DD + j]; }
  if (tid==0) dcnt = 0;
  int cb = tid>>4, cp = tid&15;
  float lm = -FLT_MAX;
  for (int k=cp;k<NBLK;k+=16) lm = fmaxf(lm, g_pmax[k*16+cb]);
  red2[cb][cp] = lm; __syncthreads();
  if (cp==0){ float m2=red2[cb][0]; for (int z=1;z<16;z++) m2=fmaxf(m2,red2[cb][z]); sgm[cb]=m2; }
  __syncthreads();
  float ls = 0.f;
  for (int k=cp;k<NBLK;k+=16) ls += g_psum[k*16+cb]*expf(g_pmax[k*16+cb]-sgm[cb]);
  red2[cb][cp] = ls; __syncthreads();
  if (cp==0){ float s2=0.f; for (int z=0;z<16;z++) s2+=red2[cb][z]; sginv[cb]=1.f/s2; }
  __syncthreads();
  int b = tid&15, r = tid>>4;
  attn_s[b][r] = expf(g_scores[b*MM + m0 + r] - sgm[b]) * sginv[b];
  int s = g_slot[b*MM + m0 + r];
  if (s >= 0){ int p = atomicAdd(&dcnt,1); dlist[p] = (b<<16)|(r<<12)|s; }
  __syncthreads();
  float acc[16];
  #pragma unroll
  for (int z=0;z<16;z++) acc[z]=0.f;
  #pragma unroll 4
  for (int rr=0;rr<16;rr++){
    float rv = rows[rr][tid];
    #pragma unroll
    for (int bz=0;bz<16;bz++) acc[bz] = fmaf(attn_s[bz][rr], rv, acc[bz]);
  }
  #pragma unroll
  for (int bz=0;bz<16;bz++) spart[bz][tid] = acc[bz];
  __syncthreads();
  int wid = tid>>5, lane = tid&31;
  int dn = dcnt;
  for (int e=wid; e<dn; e+=8){
    int pk = dlist[e]; int eb = pk>>16, er = (pk>>12)&15, es = pk&0xfff;
    const float* ov = g_ovl + ((size_t)eb*OV + es)*DD;
    float a = attn_s[eb][er];
    #pragma unroll
    for (int k=0;k<8;k++){ int d = lane+32*k; atomicAdd(&spart[eb][d], a*(ov[d]-rows[er][d])); }
  }
  __syncthreads();
  for (int i=tid;i<16*DD;i+=256) g_partial[(size_t)blk*16*DD + i] = ((float*)spart)[i];
}

// reduce -> h -> memout -> out; gate; top8; slot assign; row update
__global__ void k4(const float* __restrict__ base, const float* __restrict__ x,
                   const float* __restrict__ bv, float* __restrict__ out, int t){
  __shared__ float hs[DD], ms[DD], xt_s[DD], gate_s[DD];
  __shared__ float ss[MM];
  __shared__ float rv[8]; __shared__ int ri[8];
  __shared__ int idxs[TK], prevs[TK], slots[TK];
  int b = blockIdx.x, tid = threadIdx.x;
  float h = 0.f;
  #pragma unroll 4
  for (int k2=0;k2<NBLK;k2++) h += g_partial[((size_t)k2*16+b)*DD + tid];
  hs[tid] = h;
  xt_s[tid] = x[((size_t)b*SS+t)*DD + tid];
  for (int i=tid;i<MM;i+=256) ss[i] = g_scores[b*MM + i];
  __syncthreads();
  float mo = 0.f;
  #pragma unroll 4
  for (int j=0;j<DD;j++) mo = fmaf(g_WvT[j*DD+tid], hs[j], mo);
  mo += bv[tid];
  ms[tid] = mo;
  out[((size_t)b*SS+t)*DD + tid] = mo;
  __syncthreads();
  float gp = g_gx[((size_t)t*BB+b)*DD + tid];
  #pragma unroll 4
  for (int j=0;j<DD;j++) gp = fmaf(g_WuT2[j*DD+tid], ms[j], gp);
  gate_s[tid] = 1.f/(1.f+expf(-gp));
  int wid = tid>>5, lane = tid&31;
  for (int k2=0;k2<TK;k2++){
    float v = -FLT_MAX; int bi = MM;
    #pragma unroll
    for (int m=tid;m<MM;m+=256){ float s2 = ss[m]; if (s2 > v){ v=s2; bi=m; } }
    #pragma unroll
    for (int off=16; off; off>>=1){
      float ov2 = __shfl_xor_sync(0xffffffffu, v, off);
      int   oi  = __shfl_xor_sync(0xffffffffu, bi, off);
      if (ov2 > v || (ov2==v && oi<bi)){ v=ov2; bi=oi; }
    }
    if (lane==0){ rv[wid]=v; ri[wid]=bi; }
    __syncthreads();
    if (tid==0){
      float bv2 = rv[0]; int bi2 = ri[0];
      for (int w=1;w<8;w++){ if (rv[w]>bv2 || (rv[w]==bv2 && ri[w]<bi2)){ bv2=rv[w]; bi2=ri[w]; } }
      idxs[k2] = bi2; ss[bi2] = -FLT_MAX;
    }
    __syncthreads();
  }
  if (tid==0){
    int cnt = g_ovcnt[b];
    for (int i=0;i<TK;i++){
      int row = idxs[i]; int s = g_slot[b*MM+row];
      prevs[i] = s;
      if (s < 0){ s = cnt++; g_slot[b*MM+row] = s; }
      slots[i] = s;
    }
    g_ovcnt[b] = cnt;
  }
  __syncthreads();
  float g = gate_s[tid];
  float xd = xt_s[tid];
  #pragma unroll
  for (int i=0;i<TK;i++){
    int row = idxs[i];
    float old = (prevs[i] < 0) ? base[(size_t)row*DD + tid]
                               : g_ovl[((size_t)b*OV + prevs[i])*DD + tid];
    g_ovl[((size_t)b*OV + slots[i])*DD + tid] = old + g*(xd - old);
  }
}

// ---------------- launch ----------------

extern "C" void kernel_launch(void* const* d_in, const int* in_sizes, int n_in,
                              void* d_out, int out_size){
  const float* x      = (const float*)d_in[0];
  const float* memory = (const float*)d_in[1];
  const float* Wq     = (const float*)d_in[2];
  const float* bq     = (const float*)d_in[3];
  const float* Wk     = (const float*)d_in[4];
  // bk (d_in[5]) contributes only a softmax-invariant constant -> dropped
  const float* Wv     = (const float*)d_in[6];
  const float* bv     = (const float*)d_in[7];
  const float* Wu     = (const float*)d_in[8];
  const float* bu     = (const float*)d_in[9];
  float* out = (float*)d_out;

  p_trans<<<dim3(8,8,3), dim3(32,8)>>>(Wv, Wu);
  p_A<<<DD+1, 256>>>(Wq, Wk, bq);
  p_slot<<<128, 256>>>();
  p_qk<<<dim3(SS,2), 256>>>(x, bu);

  for (int t=0; t<SS; t++){
    k1<<<NBLK, 256>>>(memory, t);
    k3<<<NBLK, 256>>>(memory, t);
    k4<<<BB, 256>>>(memory, x, bv, out, t);
  }
}

// round 4
// speedup vs baseline: 1.7722x; 1.7722x over previous
#include <cuda_runtime.h>
#include <math.h>
#include <float.h>

#define BB 16
#define SS 64
#define MM 2048
#define DD 256
#define TK 8
#define OV 512
#define NB 128
#define SCALE 0.0625f

// ---- persistent state (re-initialized every launch; no runtime allocs) ----
__device__ float g_ovl[BB*OV*DD];
__device__ int   g_slot[BB*MM];
__device__ int   g_ovcnt[BB];
__device__ float g_qk[SS*BB*DD];
__device__ float g_gx[SS*BB*DD];
__device__ float g_AT[DD*DD];
__device__ float g_avec[DD];
__device__ float g_WuT1[DD*DD];
__device__ float g_WuT2[DD*DD];
__device__ float g_WvT[DD*DD];
__device__ float g_W2c[DD*DD];
__device__ float g_cvec[DD];
__device__ float g_scores[BB*MM];
__device__ float g_pmax[NB*BB];
__device__ float g_psum[NB*BB];
__device__ float g_partial[NB*BB*DD];
__device__ float g_h[BB*DD];
__device__ int   g_tk[BB*24];
__device__ volatile int g_arr[NB];
__device__ volatile int g_gen;

// ---------------- init kernels ----------------

__global__ void p_trans(const float* __restrict__ Wv, const float* __restrict__ Wu){
  __shared__ float tile[32][33];
  int which = blockIdx.z;
  const float* src; int stride; float* dst;
  if (which==0){ src=Wv; stride=DD;   dst=g_WvT;  }
  else if (which==1){ src=Wu; stride=2*DD; dst=g_WuT1; }
  else { src=Wu+DD; stride=2*DD; dst=g_WuT2; }
  int bi=blockIdx.x*32, bj=blockIdx.y*32;
  int tx=threadIdx.x, ty=threadIdx.y;
  #pragma unroll
  for (int k=0;k<32;k+=8) tile[ty+k][tx] = src[(size_t)(bi+ty+k)*stride + bj+tx];
  __syncthreads();
  #pragma unroll
  for (int k=0;k<32;k+=8) dst[(size_t)(bj+ty+k)*DD + bi+tx] = tile[tx][ty+k];
}

__global__ void p_A(const float* __restrict__ Wq, const float* __restrict__ Wk,
                    const float* __restrict__ bq){
  __shared__ float col[DD];
  int j = blockIdx.x, tid = threadIdx.x;
  col[tid] = (j < DD) ? Wq[(size_t)tid*DD + j] : bq[tid];
  __syncthreads();
  float acc = 0.f;
  #pragma unroll 4
  for (int i=0;i<DD;i++) acc = fmaf(Wk[(size_t)i*DD+tid], col[i], acc);
  if (j < DD) g_AT[j*DD+tid] = acc*SCALE;
  else        g_avec[tid]    = acc*SCALE;
}

// W2c[i][d] = sum_j WvT[i][j]*Wu2T[j][d];  cvec[d] = sum_j bv[j]*Wu2T[j][d]
__global__ void p_W2(const float* __restrict__ bv){
  __shared__ float col[DD];
  int i = blockIdx.x, tid = threadIdx.x;
  col[tid] = (i < DD) ? g_WvT[i*DD+tid] : bv[tid];
  __syncthreads();
  float acc = 0.f;
  #pragma unroll 4
  for (int j=0;j<DD;j++) acc = fmaf(g_WuT2[j*DD+tid], col[j], acc);
  if (i < DD) g_W2c[i*DD+tid] = acc;
  else        g_cvec[tid]     = acc;
}

__global__ void p_slot(){
  int i = blockIdx.x*256 + threadIdx.x;
  if (i < BB*MM) g_slot[i] = -1;
  if (i < BB)    g_ovcnt[i] = 0;
  if (i < NB)    ((int*)g_arr)[i] = 0;
  if (i == 0)    *((int*)&g_gen) = 0;
}

__global__ void p_qk(const float* __restrict__ x, const float* __restrict__ bu){
  __shared__ __align__(16) float xsT[DD][8];
  int t=blockIdx.x, which=blockIdx.y, bh=blockIdx.z, tid=threadIdx.x;
  int b0 = bh*8;
  for (int i=tid;i<8*DD;i+=256){ int b=i>>8, j=i&255; xsT[j][b] = x[((size_t)(b0+b)*SS+t)*DD + j]; }
  __syncthreads();
  const float* W = (which==0) ? g_AT : g_WuT1;
  float acc[8];
  #pragma unroll
  for (int b=0;b<8;b++) acc[b]=0.f;
  #pragma unroll 4
  for (int j=0;j<DD;j++){
    float w = W[j*DD+tid];
    float4 xa = *(const float4*)&xsT[j][0];
    float4 xb = *(const float4*)&xsT[j][4];
    acc[0]=fmaf(w,xa.x,acc[0]); acc[1]=fmaf(w,xa.y,acc[1]);
    acc[2]=fmaf(w,xa.z,acc[2]); acc[3]=fmaf(w,xa.w,acc[3]);
    acc[4]=fmaf(w,xb.x,acc[4]); acc[5]=fmaf(w,xb.y,acc[5]);
    acc[6]=fmaf(w,xb.z,acc[6]); acc[7]=fmaf(w,xb.w,acc[7]);
  }
  if (which==0){
    float av = g_avec[tid];
    #pragma unroll
    for (int b=0;b<8;b++) g_qk[((size_t)t*BB + b0+b)*DD + tid] = acc[b]+av;
  } else {
    float bb = bu[tid];
    #pragma unroll
    for (int b=0;b<8;b++) g_gx[((size_t)t*BB + b0+b)*DD + tid] = acc[b]+bb;
  }
}

// ---------------- grid barrier ----------------

__device__ __forceinline__ void gsync(int bid, int blk, int tid){
  __threadfence();
  __syncthreads();
  if (blk == 0){
    if (tid > 0 && tid < NB){
      while (g_arr[tid] < bid) __nanosleep(64);
    }
    __syncthreads();
    if (tid == 0){ __threadfence(); g_gen = bid; }
  } else {
    if (tid == 0){
      g_arr[blk] = bid;
      while (g_gen < bid) __nanosleep(64);
      __threadfence();
    }
  }
  __syncthreads();
}

// ---------------- the persistent kernel ----------------

__global__ void __launch_bounds__(256, 1)
persist(const float* __restrict__ base, const float* __restrict__ x,
        const float* __restrict__ bv, float* __restrict__ out){
  __shared__ __align__(16) float rows[16][260];
  __shared__ __align__(16) float buf[16*260];     // A: qks[16][260]; B: spart[16][256]
  __shared__ float sc[16][17];
  __shared__ __align__(16) float attn_s[16][24];
  __shared__ float red2[16][17];                  // also C2 gp reduce (flat 272)
  __shared__ float redc[256];
  __shared__ float sgm_s[16], sginv_s[16];
  __shared__ int   dlist[256];
  __shared__ int   dcnt_s;
  __shared__ float warrv[8]; __shared__ int warri[8];
  __shared__ int   idxs_s[TK];
  __shared__ int   chosen_s;
  __shared__ float hs[DD];
  __shared__ int   tk_s[24];
  __shared__ float gatec[32];

  int blk = blockIdx.x, tid = threadIdx.x;
  int m0 = blk*16;
  int wid = tid>>5, lane = tid&31;
  int b2 = blk>>3, sub = blk&7;

  // base rows resident in smem for the whole run
  for (int i=tid;i<16*DD;i+=256){ int r=i>>8, j=i&255; rows[r][j] = base[(size_t)(m0+r)*DD + j]; }

  int bid = 0;
  for (int t=0;t<SS;t++){
    // ================= Phase A: scores =================
    float (*qks)[260] = (float(*)[260])buf;
    const float* qkt = g_qk + (size_t)t*BB*DD;
    for (int i=tid;i<16*DD;i+=256){ int b=i>>8, j=i&255; qks[b][j] = qkt[i]; }
    if (tid==0) dcnt_s = 0;
    __syncthreads();
    int b = tid&15, r = tid>>4;
    {
      const float4* rp = (const float4*)&rows[r][0];
      const float4* qp = (const float4*)&qks[b][0];
      float4 a4 = make_float4(0.f,0.f,0.f,0.f);
      #pragma unroll 16
      for (int j4=0;j4<64;j4++){
        float4 rv4 = rp[j4], qv4 = qp[j4];
        a4.x = fmaf(rv4.x,qv4.x,a4.x); a4.y = fmaf(rv4.y,qv4.y,a4.y);
        a4.z = fmaf(rv4.z,qv4.z,a4.z); a4.w = fmaf(rv4.w,qv4.w,a4.w);
      }
      sc[b][r] = (a4.x+a4.y)+(a4.z+a4.w);
      int s = __ldcg(&g_slot[b*MM + m0 + r]);
      if (s >= 0){ int p = atomicAdd(&dcnt_s,1); dlist[p] = (b<<16)|(r<<12)|s; }
    }
    __syncthreads();
    int dn = dcnt_s;
    for (int e=wid; e<dn; e+=8){
      int pk = dlist[e]; int eb = pk>>16, er = (pk>>12)&15, es = pk&0xfff;
      const float* ov = g_ovl + ((size_t)eb*OV + es)*DD;
      float a2 = 0.f;
      #pragma unroll
      for (int k=0;k<8;k++) a2 = fmaf(__ldcg(&ov[lane+32*k]), qks[eb][lane+32*k], a2);
      #pragma unroll
      for (int off=16; off; off>>=1) a2 += __shfl_xor_sync(0xffffffffu, a2, off);
      if (lane==0) sc[eb][er] = a2;
    }
    __syncthreads();
    __stcg(&g_scores[b*MM + m0 + r], sc[b][r]);
    if (tid < 16){
      float mx = -FLT_MAX;
      #pragma unroll
      for (int rr=0;rr<16;rr++) mx = fmaxf(mx, sc[tid][rr]);
      float sm = 0.f;
      #pragma unroll
      for (int rr=0;rr<16;rr++) sm += expf(sc[tid][rr]-mx);
      __stcg(&g_pmax[blk*16+tid], mx);
      __stcg(&g_psum[blk*16+tid], sm);
    }
    gsync(++bid, blk, tid);

    // ================= Phase B: attn + h partials =================
    {
      int cb = tid>>4, cp = tid&15;
      float lm = -FLT_MAX;
      for (int k=cp;k<NB;k+=16) lm = fmaxf(lm, __ldcg(&g_pmax[k*16+cb]));
      red2[cb][cp] = lm; __syncthreads();
      if (cp==0){ float m2=red2[cb][0]; for (int z=1;z<16;z++) m2=fmaxf(m2,red2[cb][z]); sgm_s[cb]=m2; }
      __syncthreads();
      float ls = 0.f;
      for (int k=cp;k<NB;k+=16) ls += __ldcg(&g_psum[k*16+cb])*expf(__ldcg(&g_pmax[k*16+cb])-sgm_s[cb]);
      red2[cb][cp] = ls; __syncthreads();
      if (cp==0){ float s2=0.f; for (int z=0;z<16;z++) s2+=red2[cb][z]; sginv_s[cb]=1.f/s2; }
      __syncthreads();
      attn_s[b][r] = expf(sc[b][r]-sgm_s[b])*sginv_s[b];
      __syncthreads();
      float rv[16];
      #pragma unroll
      for (int rr=0;rr<16;rr++) rv[rr] = rows[rr][tid];
      float (*spart)[256] = (float(*)[256])buf;   // overwrites qks (dead)
      #pragma unroll
      for (int bz=0;bz<16;bz++){
        float4 a0 = *(const float4*)&attn_s[bz][0];
        float4 a1 = *(const float4*)&attn_s[bz][4];
        float4 a2v= *(const float4*)&attn_s[bz][8];
        float4 a3 = *(const float4*)&attn_s[bz][12];
        float acc =  a0.x*rv[0]+a0.y*rv[1]+a0.z*rv[2]+a0.w*rv[3];
        acc = fmaf(a1.x,rv[4],acc);  acc = fmaf(a1.y,rv[5],acc);
        acc = fmaf(a1.z,rv[6],acc);  acc = fmaf(a1.w,rv[7],acc);
        acc = fmaf(a2v.x,rv[8],acc); acc = fmaf(a2v.y,rv[9],acc);
        acc = fmaf(a2v.z,rv[10],acc);acc = fmaf(a2v.w,rv[11],acc);
        acc = fmaf(a3.x,rv[12],acc); acc = fmaf(a3.y,rv[13],acc);
        acc = fmaf(a3.z,rv[14],acc); acc = fmaf(a3.w,rv[15],acc);
        spart[bz][tid] = acc;
      }
      __syncthreads();
      for (int e=wid; e<dn; e+=8){
        int pk = dlist[e]; int eb = pk>>16, er = (pk>>12)&15, es = pk&0xfff;
        const float* ov = g_ovl + ((size_t)eb*OV + es)*DD;
        float a = attn_s[eb][er];
        #pragma unroll
        for (int k=0;k<8;k++){ int d = lane+32*k; atomicAdd(&spart[eb][d], a*(__ldcg(&ov[d])-rows[er][d])); }
      }
      __syncthreads();
      for (int i=tid;i<16*256;i+=256) __stcg(&g_partial[(size_t)blk*16*256 + i], buf[i]);
    }
    gsync(++bid, blk, tid);

    // ================= Phase C1: h reduce + top8 + slots =================
    {
      int dl = tid&31, kg = tid>>5;
      int d = sub*32 + dl;
      float hv = 0.f;
      for (int k=kg;k<NB;k+=8) hv += __ldcg(&g_partial[((size_t)k*16 + b2)*256 + d]);
      redc[tid] = hv; __syncthreads();
      if (kg==0){
        float s2 = 0.f;
        #pragma unroll
        for (int z=0;z<8;z++) s2 += redc[z*32+dl];
        __stcg(&g_h[b2*DD+d], s2);
      }
      if (sub==0){
        float vloc[8];
        int base_m = tid*8;
        #pragma unroll
        for (int k=0;k<8;k++) vloc[k] = __ldcg(&g_scores[b2*MM + base_m + k]);
        for (int round=0; round<TK; round++){
          float v = -FLT_MAX; int bi2 = MM;
          #pragma unroll
          for (int k=0;k<8;k++){ if (vloc[k] > v){ v = vloc[k]; bi2 = base_m+k; } }
          #pragma unroll
          for (int off=16; off; off>>=1){
            float ov2 = __shfl_xor_sync(0xffffffffu, v, off);
            int   oi  = __shfl_xor_sync(0xffffffffu, bi2, off);
            if (ov2 > v || (ov2==v && oi<bi2)){ v=ov2; bi2=oi; }
          }
          if (lane==0){ warrv[wid]=v; warri[wid]=bi2; }
          __syncthreads();
          if (tid==0){
            float bv2 = warrv[0]; int bj = warri[0];
            for (int w=1;w<8;w++){
              if (warrv[w]>bv2 || (warrv[w]==bv2 && warri[w]<bj)){ bv2=warrv[w]; bj=warri[w]; }
            }
            idxs_s[round] = bj; chosen_s = bj;
          }
          __syncthreads();
          int ch = chosen_s;
          if ((ch>>3) == tid) vloc[ch&7] = -FLT_MAX;
        }
        if (tid==0){
          int cnt = __ldcg(&g_ovcnt[b2]);
          for (int i=0;i<TK;i++){
            int row = idxs_s[i];
            int s = __ldcg(&g_slot[b2*MM+row]);
            int prev = s;
            if (s < 0){ s = cnt++; __stcg(&g_slot[b2*MM+row], s); }
            __stcg(&g_tk[b2*24 + i*3 + 0], row);
            __stcg(&g_tk[b2*24 + i*3 + 1], prev);
            __stcg(&g_tk[b2*24 + i*3 + 2], s);
          }
          __stcg(&g_ovcnt[b2], cnt);
        }
      }
    }
    gsync(++bid, blk, tid);

    // ================= Phase C2: memout + gate + out + row update =================
    {
      for (int i=tid;i<DD;i+=256) hs[i] = __ldcg(&g_h[b2*DD+i]);
      if (tid < 24) tk_s[tid] = __ldcg(&g_tk[b2*24+tid]);
      __syncthreads();
      int dl = tid&31, jg = tid>>5;
      int d = sub*32 + dl;
      float mo = 0.f, gp = 0.f;
      #pragma unroll 4
      for (int j=jg; j<DD; j+=8){
        float hj = hs[j];
        mo = fmaf(g_WvT[j*DD+d], hj, mo);
        gp = fmaf(g_W2c[j*DD+d], hj, gp);
      }
      float* redg = &red2[0][0];
      redc[tid] = mo; redg[tid] = gp;
      __syncthreads();
      if (jg==0){
        float m2 = bv[d], gg = g_gx[((size_t)t*BB+b2)*DD + d] + g_cvec[d];
        #pragma unroll
        for (int z=0;z<8;z++){ m2 += redc[z*32+dl]; gg += redg[z*32+dl]; }
        out[((size_t)b2*SS+t)*DD + d] = m2;
        gatec[dl] = 1.f/(1.f+expf(-gg));
      }
      __syncthreads();
      int i = tid>>5;
      int row  = tk_s[i*3+0];
      int prev = tk_s[i*3+1];
      int slot = tk_s[i*3+2];
      float gate = gatec[dl];
      float xd = x[((size_t)b2*SS+t)*DD + d];
      float old = (prev < 0) ? __ldg(&base[(size_t)row*DD + d])
                             : __ldcg(&g_ovl[((size_t)b2*OV + prev)*DD + d]);
      __stcg(&g_ovl[((size_t)b2*OV + slot)*DD + d], old + gate*(xd-old));
    }
    gsync(++bid, blk, tid);
  }
}

// ---------------- launch ----------------

extern "C" void kernel_launch(void* const* d_in, const int* in_sizes, int n_in,
                              void* d_out, int out_size){
  const float* x      = (const float*)d_in[0];
  const float* memory = (const float*)d_in[1];
  const float* Wq     = (const float*)d_in[2];
  const float* bq     = (const float*)d_in[3];
  const float* Wk     = (const float*)d_in[4];
  // bk contributes only a softmax-invariant constant -> dropped
  const float* Wv     = (const float*)d_in[6];
  const float* bv     = (const float*)d_in[7];
  const float* Wu     = (const float*)d_in[8];
  const float* bu     = (const float*)d_in[9];
  float* out = (float*)d_out;

  p_trans<<<dim3(8,8,3), dim3(32,8)>>>(Wv, Wu);
  p_A<<<DD+1, 256>>>(Wq, Wk, bq);
  p_W2<<<DD+1, 256>>>(bv);
  p_slot<<<128, 256>>>();
  p_qk<<<dim3(SS,2,2), 256>>>(x, bu);
  persist<<<NB, 256>>>(memory, x, bv, out);
}

// round 6
// speedup vs baseline: 1.9667x; 1.1098x over previous
#include <cuda_runtime.h>
#include <math.h>
#include <float.h>

#define BB 16
#define SS 64
#define MM 2048
#define DD 256
#define TK 8
#define OV 512
#define NB 128
#define SCALE 0.0625f

// ---- persistent state (re-initialized every launch; no runtime allocs) ----
__device__ float g_ovl[BB*OV*DD];
__device__ int   g_slot[BB*MM];
__device__ int   g_ovcnt[BB];
__device__ float g_qk[SS*BB*DD];
__device__ float g_gx[SS*BB*DD];
__device__ float g_AT[DD*DD];
__device__ float g_avec[DD];
__device__ float g_WuT1[DD*DD];
__device__ float g_WuT2[DD*DD];
__device__ float g_WvT[DD*DD];
__device__ float g_W2c[DD*DD];
__device__ float g_cvec[DD];
__device__ float g_scores[BB*MM];
__device__ float g_pmax[NB*BB];
__device__ float g_psum[NB*BB];
__device__ float g_partial[NB*BB*DD];
__device__ float g_h[BB*DD];
__device__ int   g_tk[BB*24];
__device__ int   g_count;
__device__ int   g_gen2;

// ---------------- init kernels ----------------

__global__ void p_trans(const float* __restrict__ Wv, const float* __restrict__ Wu){
  __shared__ float tile[32][33];
  int which = blockIdx.z;
  const float* src; int stride; float* dst;
  if (which==0){ src=Wv; stride=DD;   dst=g_WvT;  }
  else if (which==1){ src=Wu; stride=2*DD; dst=g_WuT1; }
  else { src=Wu+DD; stride=2*DD; dst=g_WuT2; }
  int bi=blockIdx.x*32, bj=blockIdx.y*32;
  int tx=threadIdx.x, ty=threadIdx.y;
  #pragma unroll
  for (int k=0;k<32;k+=8) tile[ty+k][tx] = src[(size_t)(bi+ty+k)*stride + bj+tx];
  __syncthreads();
  #pragma unroll
  for (int k=0;k<32;k+=8) dst[(size_t)(bj+ty+k)*DD + bi+tx] = tile[tx][ty+k];
}

__global__ void p_A(const float* __restrict__ Wq, const float* __restrict__ Wk,
                    const float* __restrict__ bq){
  __shared__ float col[DD];
  int j = blockIdx.x, tid = threadIdx.x;
  col[tid] = (j < DD) ? Wq[(size_t)tid*DD + j] : bq[tid];
  __syncthreads();
  float acc = 0.f;
  #pragma unroll 4
  for (int i=0;i<DD;i++) acc = fmaf(Wk[(size_t)i*DD+tid], col[i], acc);
  if (j < DD) g_AT[j*DD+tid] = acc*SCALE;
  else        g_avec[tid]    = acc*SCALE;
}

__global__ void p_W2(const float* __restrict__ bv){
  __shared__ float col[DD];
  int i = blockIdx.x, tid = threadIdx.x;
  col[tid] = (i < DD) ? g_WvT[i*DD+tid] : bv[tid];
  __syncthreads();
  float acc = 0.f;
  #pragma unroll 4
  for (int j=0;j<DD;j++) acc = fmaf(g_WuT2[j*DD+tid], col[j], acc);
  if (i < DD) g_W2c[i*DD+tid] = acc;
  else        g_cvec[tid]     = acc;
}

__global__ void p_slot(){
  int i = blockIdx.x*256 + threadIdx.x;
  if (i < BB*MM) g_slot[i] = -1;
  if (i < BB)    g_ovcnt[i] = 0;
  if (i == 0){ g_count = 0; g_gen2 = 0; }
}

__global__ void p_qk(const float* __restrict__ x, const float* __restrict__ bu){
  __shared__ __align__(16) float xsT[DD][8];
  int t=blockIdx.x, which=blockIdx.y, bh=blockIdx.z, tid=threadIdx.x;
  int b0 = bh*8;
  for (int i=tid;i<8*DD;i+=256){ int b=i>>8, j=i&255; xsT[j][b] = x[((size_t)(b0+b)*SS+t)*DD + j]; }
  __syncthreads();
  const float* W = (which==0) ? g_AT : g_WuT1;
  float acc[8];
  #pragma unroll
  for (int b=0;b<8;b++) acc[b]=0.f;
  #pragma unroll 4
  for (int j=0;j<DD;j++){
    float w = W[j*DD+tid];
    float4 xa = *(const float4*)&xsT[j][0];
    float4 xb = *(const float4*)&xsT[j][4];
    acc[0]=fmaf(w,xa.x,acc[0]); acc[1]=fmaf(w,xa.y,acc[1]);
    acc[2]=fmaf(w,xa.z,acc[2]); acc[3]=fmaf(w,xa.w,acc[3]);
    acc[4]=fmaf(w,xb.x,acc[4]); acc[5]=fmaf(w,xb.y,acc[5]);
    acc[6]=fmaf(w,xb.z,acc[6]); acc[7]=fmaf(w,xb.w,acc[7]);
  }
  if (which==0){
    float av = g_avec[tid];
    #pragma unroll
    for (int b=0;b<8;b++) g_qk[((size_t)t*BB + b0+b)*DD + tid] = acc[b]+av;
  } else {
    float bb = bu[tid];
    #pragma unroll
    for (int b=0;b<8;b++) g_gx[((size_t)t*BB + b0+b)*DD + tid] = acc[b]+bb;
  }
}

// ---------------- fast grid barrier (acq/rel, no fences, no nanosleep) ----------------

__device__ __forceinline__ void gbar(int target){
  __syncthreads();
  if (threadIdx.x == 0){
    int old;
    asm volatile("atom.acq_rel.gpu.global.add.s32 %0, [%1], %2;"
                 : "=r"(old) : "l"(&g_count), "r"(1) : "memory");
    if (old == target*NB - 1){
      asm volatile("st.release.gpu.global.s32 [%0], %1;"
                   :: "l"(&g_gen2), "r"(target) : "memory");
    } else {
      int g;
      do {
        asm volatile("ld.acquire.gpu.global.s32 %0, [%1];"
                     : "=r"(g) : "l"(&g_gen2) : "memory");
      } while (g < target);
    }
  }
  __syncthreads();
}

// fma of two float4s into scalar accumulator (no macro token pitfalls)
__device__ __forceinline__ float dot4acc(float4 a, float4 b, float acc){
  acc = fmaf(a.x, b.x, acc);
  acc = fmaf(a.y, b.y, acc);
  acc = fmaf(a.z, b.z, acc);
  acc = fmaf(a.w, b.w, acc);
  return acc;
}

// ---------------- the persistent kernel ----------------

__global__ void __launch_bounds__(256, 1)
persist(const float* __restrict__ base, const float* __restrict__ x,
        const float* __restrict__ bv, float* __restrict__ out){
  __shared__ __align__(16) float rows[16][260];
  __shared__ __align__(16) float buf[16*260];     // A: qks[16][260]; B: spart[16][256]
  __shared__ float sc[16][17];
  __shared__ __align__(16) float attn_s[16][24];
  __shared__ float red2[16][17];
  __shared__ float redc[256];
  __shared__ float sgm_s[16], sginv_s[16];
  __shared__ int   dlist[256];
  __shared__ int   dcnt_s;
  __shared__ float warrv[8]; __shared__ int warri[8];
  __shared__ int   idxs_s[TK];
  __shared__ int   chosen_s;
  __shared__ float hs[DD];
  __shared__ int   tk_s[24];
  __shared__ float gatec[32];

  int blk = blockIdx.x, tid = threadIdx.x;
  int m0 = blk*16;
  int wid = tid>>5, lane = tid&31;
  int b2 = blk>>3, sub = blk&7;

  // base rows resident in smem for the whole run
  for (int i=tid;i<16*DD;i+=256){ int r=i>>8, j=i&255; rows[r][j] = base[(size_t)(m0+r)*DD + j]; }

  int bid = 0;
  for (int t=0;t<SS;t++){
    // ================= Phase A: scores =================
    float (*qks)[260] = (float(*)[260])buf;
    const float* qkt = g_qk + (size_t)t*BB*DD;
    for (int i=tid;i<16*DD;i+=256){ int b=i>>8, j=i&255; qks[b][j] = qkt[i]; }
    if (tid==0) dcnt_s = 0;
    __syncthreads();
    {
      int b = tid>>4, r = tid&15;
      int s = __ldcg(&g_slot[b*MM + m0 + r]);
      if (s >= 0){ int p = atomicAdd(&dcnt_s,1); dlist[p] = (b<<16)|(r<<12)|s; }
    }
    // tiled 16x16x256 GEMM: thread = (jq, bq, rq); 4x4 outputs, j split 16 ways
    {
      int jq = tid&15, bq0 = ((tid>>4)&3)*4, r0 = (tid>>6)*4;
      float acc[16];
      #pragma unroll
      for (int zz=0;zz<16;zz++) acc[zz]=0.f;
      #pragma unroll
      for (int jj=0;jj<4;jj++){
        int jb = jj*64 + jq*4;
        float4 qa[4], ra[4];
        #pragma unroll
        for (int u=0;u<4;u++){
          qa[u] = *(const float4*)&qks[bq0+u][jb];
          ra[u] = *(const float4*)&rows[r0+u][jb];
        }
        #pragma unroll
        for (int bi=0;bi<4;bi++)
          #pragma unroll
          for (int ri=0;ri<4;ri++)
            acc[bi*4+ri] = dot4acc(qa[bi], ra[ri], acc[bi*4+ri]);
      }
      #pragma unroll
      for (int off=8; off; off>>=1){
        #pragma unroll
        for (int zz=0;zz<16;zz++) acc[zz] += __shfl_xor_sync(0xffffffffu, acc[zz], off);
      }
      if (jq==0){
        #pragma unroll
        for (int bi=0;bi<4;bi++)
          #pragma unroll
          for (int ri=0;ri<4;ri++) sc[bq0+bi][r0+ri] = acc[bi*4+ri];
      }
    }
    __syncthreads();
    int dn = dcnt_s;
    for (int e=wid; e<dn; e+=8){
      int pk = dlist[e]; int eb = pk>>16, er = (pk>>12)&15, es = pk&0xfff;
      const float* ov = g_ovl + ((size_t)eb*OV + es)*DD;
      float a2 = 0.f;
      #pragma unroll
      for (int k=0;k<8;k++) a2 = fmaf(__ldcg(&ov[lane+32*k]), qks[eb][lane+32*k], a2);
      #pragma unroll
      for (int off=16; off; off>>=1) a2 += __shfl_xor_sync(0xffffffffu, a2, off);
      if (lane==0) sc[eb][er] = a2;
    }
    __syncthreads();
    { int b = tid>>4, r = tid&15; __stcg(&g_scores[b*MM + m0 + r], sc[b][r]); }
    if (tid < 16){
      float mx = -FLT_MAX;
      #pragma unroll
      for (int rr=0;rr<16;rr++) mx = fmaxf(mx, sc[tid][rr]);
      float sm = 0.f;
      #pragma unroll
      for (int rr=0;rr<16;rr++) sm += expf(sc[tid][rr]-mx);
      __stcg(&g_pmax[blk*16+tid], mx);
      __stcg(&g_psum[blk*16+tid], sm);
    }
    gbar(++bid);

    // ================= Phase B: attn + h partials =================
    {
      int cb = tid>>4, cp = tid&15;
      float lm = -FLT_MAX;
      for (int k=cp;k<NB;k+=16) lm = fmaxf(lm, __ldcg(&g_pmax[k*16+cb]));
      red2[cb][cp] = lm; __syncthreads();
      if (cp==0){ float m2=red2[cb][0]; for (int z=1;z<16;z++) m2=fmaxf(m2,red2[cb][z]); sgm_s[cb]=m2; }
      __syncthreads();
      float ls = 0.f;
      for (int k=cp;k<NB;k+=16) ls += __ldcg(&g_psum[k*16+cb])*expf(__ldcg(&g_pmax[k*16+cb])-sgm_s[cb]);
      red2[cb][cp] = ls; __syncthreads();
      if (cp==0){ float s2=0.f; for (int z=0;z<16;z++) s2+=red2[cb][z]; sginv_s[cb]=1.f/s2; }
      __syncthreads();
      int b = tid>>4, r = tid&15;
      attn_s[b][r] = expf(sc[b][r]-sgm_s[b])*sginv_s[b];
      __syncthreads();
      float rv[16];
      #pragma unroll
      for (int rr=0;rr<16;rr++) rv[rr] = rows[rr][tid];
      float (*spart)[256] = (float(*)[256])buf;
      #pragma unroll
      for (int bz=0;bz<16;bz++){
        float4 a0 = *(const float4*)&attn_s[bz][0];
        float4 a1 = *(const float4*)&attn_s[bz][4];
        float4 a2v= *(const float4*)&attn_s[bz][8];
        float4 a3 = *(const float4*)&attn_s[bz][12];
        float acc =  a0.x*rv[0]+a0.y*rv[1]+a0.z*rv[2]+a0.w*rv[3];
        acc = fmaf(a1.x,rv[4],acc);  acc = fmaf(a1.y,rv[5],acc);
        acc = fmaf(a1.z,rv[6],acc);  acc = fmaf(a1.w,rv[7],acc);
        acc = fmaf(a2v.x,rv[8],acc); acc = fmaf(a2v.y,rv[9],acc);
        acc = fmaf(a2v.z,rv[10],acc);acc = fmaf(a2v.w,rv[11],acc);
        acc = fmaf(a3.x,rv[12],acc); acc = fmaf(a3.y,rv[13],acc);
        acc = fmaf(a3.z,rv[14],acc); acc = fmaf(a3.w,rv[15],acc);
        spart[bz][tid] = acc;
      }
      __syncthreads();
      for (int e=wid; e<dn; e+=8){
        int pk = dlist[e]; int eb = pk>>16, er = (pk>>12)&15, es = pk&0xfff;
        const float* ov = g_ovl + ((size_t)eb*OV + es)*DD;
        float a = attn_s[eb][er];
        #pragma unroll
        for (int k=0;k<8;k++){ int d = lane+32*k; atomicAdd(&spart[eb][d], a*(__ldcg(&ov[d])-rows[er][d])); }
      }
      __syncthreads();
      for (int i=tid;i<16*256;i+=256) __stcg(&g_partial[(size_t)blk*16*256 + i], buf[i]);
    }
    gbar(++bid);

    // ================= Phase C1: h reduce + top8 + slots =================
    {
      int dl = tid&31, kg = tid>>5;
      int d = sub*32 + dl;
      float hv = 0.f;
      for (int k=kg;k<NB;k+=8) hv += __ldcg(&g_partial[((size_t)k*16 + b2)*256 + d]);
      redc[tid] = hv; __syncthreads();
      if (kg==0){
        float s2 = 0.f;
        #pragma unroll
        for (int z=0;z<8;z++) s2 += redc[z*32+dl];
        __stcg(&g_h[b2*DD+d], s2);
      }
      if (sub==0){
        float vloc[8];
        int base_m = tid*8;
        #pragma unroll
        for (int k=0;k<8;k++) vloc[k] = __ldcg(&g_scores[b2*MM + base_m + k]);
        for (int round=0; round<TK; round++){
          float v = -FLT_MAX; int bi2 = MM;
          #pragma unroll
          for (int k=0;k<8;k++){ if (vloc[k] > v){ v = vloc[k]; bi2 = base_m+k; } }
          #pragma unroll
          for (int off=16; off; off>>=1){
            float ov2 = __shfl_xor_sync(0xffffffffu, v, off);
            int   oi  = __shfl_xor_sync(0xffffffffu, bi2, off);
            if (ov2 > v || (ov2==v && oi<bi2)){ v=ov2; bi2=oi; }
          }
          if (lane==0){ warrv[wid]=v; warri[wid]=bi2; }
          __syncthreads();
          if (tid==0){
            float bv2 = warrv[0]; int bj = warri[0];
            for (int w=1;w<8;w++){
              if (warrv[w]>bv2 || (warrv[w]==bv2 && warri[w]<bj)){ bv2=warrv[w]; bj=warri[w]; }
            }
            idxs_s[round] = bj; chosen_s = bj;
          }
          __syncthreads();
          int ch = chosen_s;
          if ((ch>>3) == tid) vloc[ch&7] = -FLT_MAX;
        }
        if (tid==0){
          int cnt = __ldcg(&g_ovcnt[b2]);
          for (int i=0;i<TK;i++){
            int row = idxs_s[i];
            int s = __ldcg(&g_slot[b2*MM+row]);
            int prev = s;
            if (s < 0){ s = cnt++; __stcg(&g_slot[b2*MM+row], s); }
            __stcg(&g_tk[b2*24 + i*3 + 0], row);
            __stcg(&g_tk[b2*24 + i*3 + 1], prev);
            __stcg(&g_tk[b2*24 + i*3 + 2], s);
          }
          __stcg(&g_ovcnt[b2], cnt);
        }
      }
    }
    gbar(++bid);

    // ================= Phase C2: memout + gate + out + row update =================
    {
      for (int i=tid;i<DD;i+=256) hs[i] = __ldcg(&g_h[b2*DD+i]);
      if (tid < 24) tk_s[tid] = __ldcg(&g_tk[b2*24+tid]);
      __syncthreads();
      int dl = tid&31, jg = tid>>5;
      int d = sub*32 + dl;
      float mo = 0.f, gp = 0.f;
      #pragma unroll 4
      for (int j=jg; j<DD; j+=8){
        float hj = hs[j];
        mo = fmaf(g_WvT[j*DD+d], hj, mo);
        gp = fmaf(g_W2c[j*DD+d], hj, gp);
      }
      float* redg = &red2[0][0];
      redc[tid] = mo; redg[tid] = gp;
      __syncthreads();
      if (jg==0){
        float m2 = bv[d], gg = g_gx[((size_t)t*BB+b2)*DD + d] + g_cvec[d];
        #pragma unroll
        for (int z=0;z<8;z++){ m2 += redc[z*32+dl]; gg += redg[z*32+dl]; }
        out[((size_t)b2*SS+t)*DD + d] = m2;
        gatec[dl] = 1.f/(1.f+expf(-gg));
      }
      __syncthreads();
      int i = tid>>5;
      int row  = tk_s[i*3+0];
      int prev = tk_s[i*3+1];
      int slot = tk_s[i*3+2];
      float gate = gatec[dl];
      float xd = x[((size_t)b2*SS+t)*DD + d];
      float old = (prev < 0) ? __ldg(&base[(size_t)row*DD + d])
                             : __ldcg(&g_ovl[((size_t)b2*OV + prev)*DD + d]);
      __stcg(&g_ovl[((size_t)b2*OV + slot)*DD + d], old + gate*(xd-old));
    }
    gbar(++bid);
  }
}

// ---------------- launch ----------------

extern "C" void kernel_launch(void* const* d_in, const int* in_sizes, int n_in,
                              void* d_out, int out_size){
  const float* x      = (const float*)d_in[0];
  const float* memory = (const float*)d_in[1];
  const float* Wq     = (const float*)d_in[2];
  const float* bq     = (const float*)d_in[3];
  const float* Wk     = (const float*)d_in[4];
  // bk contributes only a softmax-invariant constant -> dropped
  const float* Wv     = (const float*)d_in[6];
  const float* bv     = (const float*)d_in[7];
  const float* Wu     = (const float*)d_in[8];
  const float* bu     = (const float*)d_in[9];
  float* out = (float*)d_out;

  p_trans<<<dim3(8,8,3), dim3(32,8)>>>(Wv, Wu);
  p_A<<<DD+1, 256>>>(Wq, Wk, bq);
  p_W2<<<DD+1, 256>>>(bv);
  p_slot<<<128, 256>>>();
  p_qk<<<dim3(SS,2,2), 256>>>(x, bu);
  persist<<<NB, 256>>>(memory, x, bv, out);
}